// round 15
// baseline (speedup 1.0000x reference)
#include <cuda_runtime.h>
#include <cuda_bf16.h>
#include <cstdint>

#define NB 256

// Scratch: [b][mod][slot(0,1,2)][640][100] fp32
__device__ float g_scr[196608000UL];
__device__ __nv_bfloat16 g_w_hi[6144000];
__device__ __nv_bfloat16 g_w_lo[6144000];
__device__ __nv_bfloat16 g_xt_hi[81920000UL];   // [b][l=100][c=3200]
__device__ __nv_bfloat16 g_xt_lo[81920000UL];

struct Params {
    const float* w[24];  // [mod][wq,wk,wv,bq,bk,bv]
};

__constant__ size_t c_offs[12] = {0, 409600, 819200, 1228800, 2048000, 2867200,
                                  3686400, 4096000, 4505600, 4915200, 5324800, 5734400};

// ---------------------------------------------------------------- helpers
__device__ __forceinline__ uint32_t smem_to_u32(const void* p) {
    uint32_t a;
    asm("{ .reg .u64 t; cvta.to.shared.u64 t, %1; cvt.u32.u64 %0, t; }" : "=r"(a) : "l"(p));
    return a;
}
__device__ __forceinline__ void ldsm4(uint32_t* r, uint32_t addr) {
    asm volatile("ldmatrix.sync.aligned.m8n8.x4.shared.b16 {%0,%1,%2,%3}, [%4];"
        : "=r"(r[0]), "=r"(r[1]), "=r"(r[2]), "=r"(r[3]) : "r"(addr));
}
__device__ __forceinline__ void ldsm2(uint32_t* r, uint32_t addr) {
    asm volatile("ldmatrix.sync.aligned.m8n8.x2.shared.b16 {%0,%1}, [%2];"
        : "=r"(r[0]), "=r"(r[1]) : "r"(addr));
}
__device__ __forceinline__ void mma16816(float* c, const uint32_t* a, uint32_t b0, uint32_t b1) {
    asm volatile("mma.sync.aligned.m16n8k16.row.col.f32.bf16.bf16.f32 "
        "{%0,%1,%2,%3}, {%4,%5,%6,%7}, {%8,%9}, {%0,%1,%2,%3};"
        : "+f"(c[0]), "+f"(c[1]), "+f"(c[2]), "+f"(c[3])
        : "r"(a[0]), "r"(a[1]), "r"(a[2]), "r"(a[3]), "r"(b0), "r"(b1));
}
__device__ __forceinline__ unsigned long long pack2(float x, float y) {
    unsigned long long r;
    asm("mov.b64 %0, {%1, %2};" : "=l"(r) : "f"(x), "f"(y));
    return r;
}
__device__ __forceinline__ void unpack2(unsigned long long v, float& x, float& y) {
    asm("mov.b64 {%0, %1}, %2;" : "=f"(x), "=f"(y) : "l"(v));
}
__device__ __forceinline__ void ffma2(unsigned long long& c, unsigned long long a, unsigned long long b) {
    asm("fma.rn.f32x2 %0, %1, %2, %0;" : "+l"(c) : "l"(a), "l"(b));
}
__device__ __forceinline__ unsigned long long lds_u64(uint32_t a) {
    unsigned long long v;
    asm volatile("ld.shared.b64 %0, [%1];" : "=l"(v) : "r"(a));
    return v;
}

// ============================================================================
// prep_w: fp32 weights -> bf16 hi/lo (wv all mods + thigh wq,wk)
// ============================================================================
__global__ void prep_w(Params p) {
    const int seg_tab[6] = {2, 3, 4, 5, 8, 11};
    const int seg = seg_tab[blockIdx.y];
    const int mod = seg / 3;
    const int Cin = (mod == 1) ? 1280 : 640;
    const float* __restrict__ w = p.w[mod * 6 + (seg % 3)];
    const size_t off = c_offs[seg];
    const size_t n = (size_t)640 * Cin;
    for (size_t i = (size_t)blockIdx.x * blockDim.x + threadIdx.x; i < n; i += (size_t)gridDim.x * blockDim.x) {
        float v = w[i];
        __nv_bfloat16 h = __float2bfloat16(v);
        g_w_hi[off + i] = h;
        g_w_lo[off + i] = __float2bfloat16(v - __bfloat162float(h));
    }
}

// ============================================================================
// prep_mm: M = Wq^T Wk -> bf16 hi/lo (mods 0,2,3)
// ============================================================================
__global__ __launch_bounds__(256) void prep_mm(Params p) {
    const int mod_tab[3] = {0, 2, 3};
    const int mod = mod_tab[blockIdx.y];
    const float* __restrict__ Wq = p.w[mod * 6 + 0];
    const float* __restrict__ Wk = p.w[mod * 6 + 1];
    const size_t moff = c_offs[mod * 3];

    const int tile = blockIdx.x;
    const int i0 = (tile / 10) * 64, j0 = (tile % 10) * 64;
    const int tid = threadIdx.x;

    __shared__ __align__(16) float Aq[32][68];
    __shared__ __align__(16) float Ak[32][68];

    const int ti = (tid / 16) * 4, tj = (tid % 16) * 4;
    float acc[4][4] = {};

    for (int o0 = 0; o0 < 640; o0 += 32) {
        for (int idx = tid; idx < 512; idx += 256) {
            int r = idx / 16, c4 = (idx % 16) * 4;
            *(float4*)&Aq[r][c4] = *(const float4*)(Wq + (size_t)(o0 + r) * 640 + i0 + c4);
            *(float4*)&Ak[r][c4] = *(const float4*)(Wk + (size_t)(o0 + r) * 640 + j0 + c4);
        }
        __syncthreads();
        #pragma unroll 8
        for (int o = 0; o < 32; o++) {
            float a[4], bv[4];
            #pragma unroll
            for (int ii = 0; ii < 4; ii++) a[ii] = Aq[o][ti + ii];
            #pragma unroll
            for (int jj = 0; jj < 4; jj++) bv[jj] = Ak[o][tj + jj];
            #pragma unroll
            for (int ii = 0; ii < 4; ii++)
                #pragma unroll
                for (int jj = 0; jj < 4; jj++) acc[ii][jj] += a[ii] * bv[jj];
        }
        __syncthreads();
    }

    #pragma unroll
    for (int ii = 0; ii < 4; ii++)
        #pragma unroll
        for (int jj = 0; jj < 4; jj++) {
            float v = acc[ii][jj];
            __nv_bfloat16 h = __float2bfloat16(v);
            size_t o = moff + (size_t)(i0 + ti + ii) * 640 + j0 + tj + jj;
            g_w_hi[o] = h;
            g_w_lo[o] = __float2bfloat16(v - __bfloat162float(h));
        }
}

// ============================================================================
// prep_x: x -> XT bf16 hi/lo
// ============================================================================
__global__ void prep_x(const float* __restrict__ x) {
    __shared__ float t[32][33];
    const int b = blockIdx.z, ct = blockIdx.x, lt = blockIdx.y;
    const int tx = threadIdx.x, ty = threadIdx.y;
    const float* xb = x + (size_t)b * 320000;
    const int l = lt * 32 + tx;
    #pragma unroll
    for (int j = 0; j < 4; j++) {
        int c = ct * 32 + ty + j * 8;
        t[ty + j * 8][tx] = (l < 100) ? xb[(size_t)c * 100 + l] : 0.0f;
    }
    __syncthreads();
    const int c_out = ct * 32 + tx;
    const size_t xtb = (size_t)b * 320000;
    #pragma unroll
    for (int j = 0; j < 4; j++) {
        int lo_ = lt * 32 + ty + j * 8;
        if (lo_ < 100) {
            float v = t[tx][ty + j * 8];
            __nv_bfloat16 h = __float2bfloat16(v);
            size_t o = xtb + (size_t)lo_ * 3200 + c_out;
            g_xt_hi[o] = h;
            g_xt_lo[o] = __float2bfloat16(v - __bfloat162float(h));
        }
    }
}

// ============================================================================
// qkv_mma: R14 body + batch-offset parameter (chunked launch).
// ============================================================================
#define STAGE  37120u
#define OFF_AH 0u
#define OFF_AL 10240u
#define OFF_BH 20480u
#define OFF_BL 28800u

__constant__ int c_emod[9]  = {0, 0, 1, 1, 1, 2, 2, 3, 3};
__constant__ int c_ewoff[9] = {0, 2, 3, 4, 5, 6, 8, 9, 11};
__constant__ int c_eslot[9] = {0, 2, 0, 1, 2, 0, 2, 0, 2};
__constant__ int c_ebias[9] = {3, 5, 9, 10, 11, 15, 17, 21, 23};

__global__ __launch_bounds__(256, 3) void qkv_mma(Params p, int b_off) {
    extern __shared__ __align__(16) char smem_raw[];
    const uint32_t sb = smem_to_u32(smem_raw);

    const int tid = threadIdx.x;
    int bid = blockIdx.x;
    const int mtile = bid % 5; bid /= 5;
    const int e     = bid % 9; bid /= 9;
    const int b     = b_off + bid;
    const int mod   = c_emod[e];

    const int Cin = (mod == 1) ? 1280 : 640;
    const int nch = Cin >> 5;
    const int mbase = mtile * 128;

    const int c0m_tab[4] = {2560, 640, 1920, 0};
    const size_t woff = c_offs[c_ewoff[e]];
    const size_t xoff = (size_t)b * 320000 + c0m_tab[mod];
    const float* __restrict__ bias = p.w[c_ebias[e]];
    float* __restrict__ O = g_scr + ((((size_t)b * 4 + mod) * 3 + c_eslot[e]) * 640 + mbase) * 100;

    const __nv_bfloat16* __restrict__ Wh = g_w_hi + woff;
    const __nv_bfloat16* __restrict__ Wl = g_w_lo + woff;
    const __nv_bfloat16* __restrict__ Xh = g_xt_hi + xoff;
    const __nv_bfloat16* __restrict__ Xl = g_xt_lo + xoff;

    for (int idx = tid; idx < 320; idx += 256) {
        int st = idx / 160, rest = idx % 160;
        int buf = rest / 80, r2 = rest % 80;
        uint32_t a = sb + (uint32_t)st * STAGE + (buf ? OFF_BL : OFF_BH)
                   + (uint32_t)(100 + r2 / 20) * 80 + (uint32_t)(r2 % 20) * 4;
        asm volatile("st.shared.b32 [%0], %1;" :: "r"(a), "r"(0) : "memory");
    }

    auto issue_chunk = [&](int st, int c) {
        const int k0 = c << 5;
        const uint32_t stg = sb + (uint32_t)st * STAGE;
        for (int idx = tid; idx < 1824; idx += 256) {
            const __nv_bfloat16* src;
            uint32_t dst;
            if (idx < 1024) {
                int buf = idx >> 9, r = (idx >> 2) & 127, seg = idx & 3;
                src = (buf ? Wl : Wh) + (size_t)(mbase + r) * Cin + k0 + seg * 8;
                dst = stg + (buf ? OFF_AL : OFF_AH) + (uint32_t)r * 80 + (uint32_t)seg * 16;
            } else {
                int j = idx - 1024;
                int n = j >> 3, rem = j & 7;
                int buf = rem >> 2, seg = rem & 3;
                src = (buf ? Xl : Xh) + (size_t)n * 3200 + k0 + seg * 8;
                dst = stg + (buf ? OFF_BL : OFF_BH) + (uint32_t)n * 80 + (uint32_t)seg * 16;
            }
            asm volatile("cp.async.cg.shared.global [%0], [%1], 16;" :: "r"(dst), "l"(src) : "memory");
        }
        asm volatile("cp.async.commit_group;" ::: "memory");
    };

    const int w = tid >> 5, lane = tid & 31;
    const int rloc = w * 16 + (lane >> 2);
    const int qd = lane & 3;

    const uint32_t aoff = (uint32_t)(w * 16 + (lane & 15)) * 80 + (uint32_t)(lane >> 4) * 16;
    const uint32_t b4off = (uint32_t)(((lane >> 4) * 8) + (lane & 7)) * 80 + (uint32_t)((lane >> 3) & 1) * 16;
    const uint32_t b2off = (uint32_t)(lane & 7) * 80 + (uint32_t)((lane >> 3) & 1) * 16;

    float acc[13][4];
    #pragma unroll
    for (int t = 0; t < 13; t++)
        #pragma unroll
        for (int i = 0; i < 4; i++) acc[t][i] = 0.0f;

    issue_chunk(0, 0);

    for (int c = 0; c < nch; c++) {
        const int s = c & 1;
        if (c + 1 < nch) {
            issue_chunk(s ^ 1, c + 1);
            asm volatile("cp.async.wait_group 1;" ::: "memory");
        } else {
            asm volatile("cp.async.wait_group 0;" ::: "memory");
        }
        __syncthreads();

        const uint32_t stg = sb + (uint32_t)s * STAGE;
        const uint32_t aAh = stg + OFF_AH + aoff;
        const uint32_t aAl = stg + OFF_AL + aoff;
        const uint32_t aBh4 = stg + OFF_BH + b4off;
        const uint32_t aBl4 = stg + OFF_BL + b4off;
        const uint32_t aBh2 = stg + OFF_BH + 7680u + b2off;
        const uint32_t aBl2 = stg + OFF_BL + 7680u + b2off;

        #pragma unroll
        for (int s16 = 0; s16 < 2; s16++) {
            const uint32_t ko = (uint32_t)s16 * 32;
            uint32_t ah[4], al[4];
            ldsm4(ah, aAh + ko);
            ldsm4(al, aAl + ko);
            #pragma unroll
            for (int pr = 0; pr < 6; pr++) {
                uint32_t bh[4], bl[4];
                ldsm4(bh, aBh4 + (uint32_t)pr * 1280 + ko);
                ldsm4(bl, aBl4 + (uint32_t)pr * 1280 + ko);
                mma16816(acc[2 * pr],     ah, bh[0], bh[1]);
                mma16816(acc[2 * pr + 1], ah, bh[2], bh[3]);
                mma16816(acc[2 * pr],     ah, bl[0], bl[1]);
                mma16816(acc[2 * pr + 1], ah, bl[2], bl[3]);
                mma16816(acc[2 * pr],     al, bh[0], bh[1]);
                mma16816(acc[2 * pr + 1], al, bh[2], bh[3]);
            }
            {
                uint32_t bh[2], bl[2];
                ldsm2(bh, aBh2 + ko);
                ldsm2(bl, aBl2 + ko);
                mma16816(acc[12], ah, bh[0], bh[1]);
                mma16816(acc[12], ah, bl[0], bl[1]);
                mma16816(acc[12], al, bh[0], bh[1]);
            }
        }
        __syncthreads();
    }

    const float bv0 = bias[mbase + rloc];
    const float bv1 = bias[mbase + rloc + 8];
    float* o0 = O + (size_t)rloc * 100;
    float* o1 = o0 + 800;
    #pragma unroll
    for (int t = 0; t < 13; t++) {
        int col = t * 8 + qd * 2;
        if (col < 100) {
            float2 v0 = make_float2(acc[t][0] + bv0, acc[t][1] + bv0);
            float2 v1 = make_float2(acc[t][2] + bv1, acc[t][3] + bv1);
            *(float2*)(o0 + col) = v0;
            *(float2*)(o1 + col) = v1;
        }
    }
}

// ============================================================================
// Pass 2: attention v4 (R9 body) + bm offset for chunked launch.
// ============================================================================
#define PT_OFF   0
#define U_OFF    10000
#define KC_OFF   3328
#define PART_OFF 16656
#define ROW_OFF  17656
#define ATTN_SMEM 71040

__global__ __launch_bounds__(256, 3) void attn_kernel(const float* __restrict__ x,
                                                      float* __restrict__ out, int bm_off) {
    extern __shared__ __align__(16) float sm[];
    const int tid = threadIdx.x;
    const int bm = bm_off + blockIdx.x;
    const int mod = bm & 3, b = bm >> 2;

    const float* __restrict__ S0 = g_scr + (size_t)bm * 192000;
    const int c0m_tab[4] = {2560, 640, 1920, 0};
    const float* __restrict__ Qp = (mod == 1)
        ? S0
        : (x + (size_t)b * 320000 + (size_t)c0m_tab[mod] * 100);
    const float* __restrict__ Kp = (mod == 1) ? (S0 + 64000) : S0;
    const float* __restrict__ V = S0 + 128000;
    float* __restrict__ O = out + ((size_t)mod * NB + b) * 64000;

    float* Pt   = sm + PT_OFF;
    float* U    = sm + U_OFF;
    float* part = sm + PART_OFF;
    float* row  = sm + ROW_OFF;
    const uint32_t u_b = smem_to_u32(U);
    const uint32_t pt_b = smem_to_u32(Pt);

    const bool act = tid < 250;
    const int lg = tid % 25;
    const int mg = tid / 25;
    const int m0 = mg * 10;

    unsigned long long acc[4][5];
    #pragma unroll
    for (int t = 0; t < 4; t++)
        #pragma unroll
        for (int j = 0; j < 5; j++) acc[t][j] = 0ULL;

    for (int c0 = 0; c0 < 640; c0 += 32) {
        for (int idx = tid; idx < 1600; idx += 256) {
            int which = idx >= 800;
            int i2 = idx - which * 800;
            int rw = i2 / 25, c4 = (i2 % 25) * 4;
            const float* src = (which ? Kp : Qp) + (size_t)(c0 + rw) * 100 + c4;
            *(float4*)(U + which * KC_OFF + rw * 104 + c4) = *(const float4*)src;
        }
        __syncthreads();
        if (act) {
            #pragma unroll 2
            for (int kk = 0; kk < 32; kk++) {
                const float* qrow = U + kk * 104;
                unsigned long long qd_[4];
                #pragma unroll
                for (int t = 0; t < 4; t++) {
                    float qv = qrow[lg + 25 * t];
                    qd_[t] = pack2(qv, qv);
                }
                const uint32_t kb = u_b + (uint32_t)(KC_OFF + kk * 104 + m0) * 4;
                #pragma unroll
                for (int j = 0; j < 5; j++) {
                    unsigned long long kv = lds_u64(kb + (uint32_t)j * 8);
                    ffma2(acc[0][j], qd_[0], kv);
                    ffma2(acc[1][j], qd_[1], kv);
                    ffma2(acc[2][j], qd_[2], kv);
                    ffma2(acc[3][j], qd_[3], kv);
                }
            }
        }
        __syncthreads();
    }

    if (act) {
        #pragma unroll
        for (int t = 0; t < 4; t++) {
            float mx = -3.4e38f;
            #pragma unroll
            for (int j = 0; j < 5; j++) {
                float lo, hi;
                unpack2(acc[t][j], lo, hi);
                mx = fmaxf(mx, fmaxf(lo, hi));
            }
            part[(lg + 25 * t) * 10 + mg] = mx;
        }
    }
    __syncthreads();
    if (tid < 100) {
        float m = -3.4e38f;
        #pragma unroll
        for (int g = 0; g < 10; g++) m = fmaxf(m, part[tid * 10 + g]);
        row[tid] = m;
    }
    __syncthreads();
    if (act) {
        #pragma unroll
        for (int t = 0; t < 4; t++) {
            float mr = row[lg + 25 * t];
            float s = 0.0f;
            #pragma unroll
            for (int j = 0; j < 5; j++) {
                float lo, hi;
                unpack2(acc[t][j], lo, hi);
                float e0 = __expf(lo - mr), e1 = __expf(hi - mr);
                s += e0 + e1;
                acc[t][j] = pack2(e0, e1);
            }
            part[(lg + 25 * t) * 10 + mg] = s;
        }
    }
    __syncthreads();
    if (tid < 100) {
        float s = 0.0f;
        #pragma unroll
        for (int g = 0; g < 10; g++) s += part[tid * 10 + g];
        row[tid] = 1.0f / s;
    }
    __syncthreads();
    if (act) {
        #pragma unroll
        for (int t = 0; t < 4; t++) {
            int l = lg + 25 * t;
            float inv = row[l];
            #pragma unroll
            for (int j = 0; j < 5; j++) {
                float lo, hi;
                unpack2(acc[t][j], lo, hi);
                int m = m0 + 2 * j;
                Pt[m * 100 + l]       = lo * inv;
                Pt[(m + 1) * 100 + l] = hi * inv;
            }
        }
    }

    const int cgC = tid % 16, igC = tid / 16;
    const bool actC = igC < 10;
    const int i0 = igC * 10;

    for (int chunk = 0; chunk < 10; chunk++) {
        __syncthreads();
        for (int idx = tid; idx < 1600; idx += 256) {
            int rw = idx / 25, c4 = (idx % 25) * 4;
            *(float4*)(U + rw * 100 + c4) =
                *(const float4*)(V + (size_t)(chunk * 64 + rw) * 100 + c4);
        }
        __syncthreads();
        if (actC) {
            unsigned long long pacc[4][5];
            #pragma unroll
            for (int u = 0; u < 4; u++)
                #pragma unroll
                for (int s = 0; s < 5; s++) pacc[u][s] = 0ULL;
            const uint32_t pb = pt_b + (uint32_t)i0 * 4;
            #pragma unroll 4
            for (int j = 0; j < 100; j++) {
                unsigned long long vd[4];
                #pragma unroll
                for (int u = 0; u < 4; u++) {
                    float vv = U[(cgC + 16 * u) * 100 + j];
                    vd[u] = pack2(vv, vv);
                }
                const uint32_t pj = pb + (uint32_t)j * 400;
                #pragma unroll
                for (int s = 0; s < 5; s++) {
                    unsigned long long pp = lds_u64(pj + (uint32_t)s * 8);
                    ffma2(pacc[0][s], vd[0], pp);
                    ffma2(pacc[1][s], vd[1], pp);
                    ffma2(pacc[2][s], vd[2], pp);
                    ffma2(pacc[3][s], vd[3], pp);
                }
            }
            #pragma unroll
            for (int u = 0; u < 4; u++) {
                int c_ = chunk * 64 + cgC + 16 * u;
                float* orow = O + (size_t)c_ * 100 + i0;
                #pragma unroll
                for (int s = 0; s < 5; s++) {
                    float a0, a1;
                    unpack2(pacc[u][s], a0, a1);
                    *(float2*)(orow + 2 * s) = make_float2(a0, a1);
                }
            }
        }
    }
}

extern "C" void kernel_launch(void* const* d_in, const int* in_sizes, int n_in,
                              void* d_out, int out_size) {
    const float* x = (const float*)d_in[0];
    float* out = (float*)d_out;
    Params p;
    for (int i = 0; i < 24; i++) p.w[i] = (const float*)d_in[1 + i];

    cudaFuncSetAttribute(qkv_mma, cudaFuncAttributeMaxDynamicSharedMemorySize, 74240);
    cudaFuncSetAttribute(qkv_mma, cudaFuncAttributePreferredSharedMemoryCarveout, 100);
    cudaFuncSetAttribute(attn_kernel, cudaFuncAttributeMaxDynamicSharedMemorySize, ATTN_SMEM);

    cudaStream_t s2;
    cudaStreamCreateWithFlags(&s2, cudaStreamNonBlocking);
    cudaEvent_t evQ[4], evJoin;
    for (int i = 0; i < 4; i++) cudaEventCreateWithFlags(&evQ[i], cudaEventDisableTiming);
    cudaEventCreateWithFlags(&evJoin, cudaEventDisableTiming);

    prep_w<<<dim3(800, 6), 256>>>(p);
    prep_mm<<<dim3(100, 3), 256>>>(p);
    prep_x<<<dim3(100, 4, 256), dim3(32, 8)>>>(x);

    // Pipelined chunks: qkv(i) on capture stream, attn(i) on side stream.
    for (int i = 0; i < 4; i++) {
        qkv_mma<<<2880, 256, 74240>>>(p, i * 64);
        cudaEventRecord(evQ[i], 0);
        cudaStreamWaitEvent(s2, evQ[i], 0);
        attn_kernel<<<256, 256, ATTN_SMEM, s2>>>(x, out, i * 256);
    }
    cudaEventRecord(evJoin, s2);
    cudaStreamWaitEvent(0, evJoin, 0);

    for (int i = 0; i < 4; i++) cudaEventDestroy(evQ[i]);
    cudaEventDestroy(evJoin);
    cudaStreamDestroy(s2);
}

// round 16
// speedup vs baseline: 1.0529x; 1.0529x over previous
#include <cuda_runtime.h>
#include <cuda_bf16.h>
#include <cstdint>

#define NB 256

// Scratch: [b][mod][slot(0,1,2)][640][100] fp32
__device__ float g_scr[196608000UL];
__device__ __nv_bfloat16 g_w_hi[6144000];
__device__ __nv_bfloat16 g_w_lo[6144000];
__device__ __nv_bfloat16 g_xt_hi[81920000UL];   // [b][l=100][c=3200]
__device__ __nv_bfloat16 g_xt_lo[81920000UL];

struct Params {
    const float* w[24];  // [mod][wq,wk,wv,bq,bk,bv]
};

__constant__ size_t c_offs[12] = {0, 409600, 819200, 1228800, 2048000, 2867200,
                                  3686400, 4096000, 4505600, 4915200, 5324800, 5734400};

// ---------------------------------------------------------------- helpers
__device__ __forceinline__ uint32_t smem_to_u32(const void* p) {
    uint32_t a;
    asm("{ .reg .u64 t; cvta.to.shared.u64 t, %1; cvt.u32.u64 %0, t; }" : "=r"(a) : "l"(p));
    return a;
}
__device__ __forceinline__ void ldsm4(uint32_t* r, uint32_t addr) {
    asm volatile("ldmatrix.sync.aligned.m8n8.x4.shared.b16 {%0,%1,%2,%3}, [%4];"
        : "=r"(r[0]), "=r"(r[1]), "=r"(r[2]), "=r"(r[3]) : "r"(addr));
}
__device__ __forceinline__ void ldsm2(uint32_t* r, uint32_t addr) {
    asm volatile("ldmatrix.sync.aligned.m8n8.x2.shared.b16 {%0,%1}, [%2];"
        : "=r"(r[0]), "=r"(r[1]) : "r"(addr));
}
__device__ __forceinline__ void mma16816(float* c, const uint32_t* a, uint32_t b0, uint32_t b1) {
    asm volatile("mma.sync.aligned.m16n8k16.row.col.f32.bf16.bf16.f32 "
        "{%0,%1,%2,%3}, {%4,%5,%6,%7}, {%8,%9}, {%0,%1,%2,%3};"
        : "+f"(c[0]), "+f"(c[1]), "+f"(c[2]), "+f"(c[3])
        : "r"(a[0]), "r"(a[1]), "r"(a[2]), "r"(a[3]), "r"(b0), "r"(b1));
}
__device__ __forceinline__ unsigned long long pack2(float x, float y) {
    unsigned long long r;
    asm("mov.b64 %0, {%1, %2};" : "=l"(r) : "f"(x), "f"(y));
    return r;
}
__device__ __forceinline__ void unpack2(unsigned long long v, float& x, float& y) {
    asm("mov.b64 {%0, %1}, %2;" : "=f"(x), "=f"(y) : "l"(v));
}
__device__ __forceinline__ void ffma2(unsigned long long& c, unsigned long long a, unsigned long long b) {
    asm("fma.rn.f32x2 %0, %1, %2, %0;" : "+l"(c) : "l"(a), "l"(b));
}
__device__ __forceinline__ unsigned long long lds_u64(uint32_t a) {
    unsigned long long v;
    asm volatile("ld.shared.b64 %0, [%1];" : "=l"(v) : "r"(a));
    return v;
}

// ============================================================================
// prep_w: fp32 weights -> bf16 hi/lo (wv all mods + thigh wq,wk)
// ============================================================================
__global__ void prep_w(Params p) {
    const int seg_tab[6] = {2, 3, 4, 5, 8, 11};
    const int seg = seg_tab[blockIdx.y];
    const int mod = seg / 3;
    const int Cin = (mod == 1) ? 1280 : 640;
    const float* __restrict__ w = p.w[mod * 6 + (seg % 3)];
    const size_t off = c_offs[seg];
    const size_t n = (size_t)640 * Cin;
    for (size_t i = (size_t)blockIdx.x * blockDim.x + threadIdx.x; i < n; i += (size_t)gridDim.x * blockDim.x) {
        float v = w[i];
        __nv_bfloat16 h = __float2bfloat16(v);
        g_w_hi[off + i] = h;
        g_w_lo[off + i] = __float2bfloat16(v - __bfloat162float(h));
    }
}

// ============================================================================
// prep_mm: M = Wq^T Wk -> bf16 hi/lo (mods 0,2,3)
// ============================================================================
__global__ __launch_bounds__(256) void prep_mm(Params p) {
    const int mod_tab[3] = {0, 2, 3};
    const int mod = mod_tab[blockIdx.y];
    const float* __restrict__ Wq = p.w[mod * 6 + 0];
    const float* __restrict__ Wk = p.w[mod * 6 + 1];
    const size_t moff = c_offs[mod * 3];

    const int tile = blockIdx.x;
    const int i0 = (tile / 10) * 64, j0 = (tile % 10) * 64;
    const int tid = threadIdx.x;

    __shared__ __align__(16) float Aq[32][68];
    __shared__ __align__(16) float Ak[32][68];

    const int ti = (tid / 16) * 4, tj = (tid % 16) * 4;
    float acc[4][4] = {};

    for (int o0 = 0; o0 < 640; o0 += 32) {
        for (int idx = tid; idx < 512; idx += 256) {
            int r = idx / 16, c4 = (idx % 16) * 4;
            *(float4*)&Aq[r][c4] = *(const float4*)(Wq + (size_t)(o0 + r) * 640 + i0 + c4);
            *(float4*)&Ak[r][c4] = *(const float4*)(Wk + (size_t)(o0 + r) * 640 + j0 + c4);
        }
        __syncthreads();
        #pragma unroll 8
        for (int o = 0; o < 32; o++) {
            float a[4], bv[4];
            #pragma unroll
            for (int ii = 0; ii < 4; ii++) a[ii] = Aq[o][ti + ii];
            #pragma unroll
            for (int jj = 0; jj < 4; jj++) bv[jj] = Ak[o][tj + jj];
            #pragma unroll
            for (int ii = 0; ii < 4; ii++)
                #pragma unroll
                for (int jj = 0; jj < 4; jj++) acc[ii][jj] += a[ii] * bv[jj];
        }
        __syncthreads();
    }

    #pragma unroll
    for (int ii = 0; ii < 4; ii++)
        #pragma unroll
        for (int jj = 0; jj < 4; jj++) {
            float v = acc[ii][jj];
            __nv_bfloat16 h = __float2bfloat16(v);
            size_t o = moff + (size_t)(i0 + ti + ii) * 640 + j0 + tj + jj;
            g_w_hi[o] = h;
            g_w_lo[o] = __float2bfloat16(v - __bfloat162float(h));
        }
}

// ============================================================================
// prep_x: x -> XT bf16 hi/lo
// ============================================================================
__global__ void prep_x(const float* __restrict__ x) {
    __shared__ float t[32][33];
    const int b = blockIdx.z, ct = blockIdx.x, lt = blockIdx.y;
    const int tx = threadIdx.x, ty = threadIdx.y;
    const float* xb = x + (size_t)b * 320000;
    const int l = lt * 32 + tx;
    #pragma unroll
    for (int j = 0; j < 4; j++) {
        int c = ct * 32 + ty + j * 8;
        t[ty + j * 8][tx] = (l < 100) ? xb[(size_t)c * 100 + l] : 0.0f;
    }
    __syncthreads();
    const int c_out = ct * 32 + tx;
    const size_t xtb = (size_t)b * 320000;
    #pragma unroll
    for (int j = 0; j < 4; j++) {
        int lo_ = lt * 32 + ty + j * 8;
        if (lo_ < 100) {
            float v = t[tx][ty + j * 8];
            __nv_bfloat16 h = __float2bfloat16(v);
            size_t o = xtb + (size_t)lo_ * 3200 + c_out;
            g_xt_hi[o] = h;
            g_xt_lo[o] = __float2bfloat16(v - __bfloat162float(h));
        }
    }
}

// ============================================================================
// qkv_mma: R14 body with single-barrier pipeline:
//   wait_group 0 -> __syncthreads -> issue(c+1) -> MMA(c)
// Barrier count halved; prefetch depth and buffer safety preserved.
// ============================================================================
#define STAGE  37120u
#define OFF_AH 0u
#define OFF_AL 10240u
#define OFF_BH 20480u
#define OFF_BL 28800u

__constant__ int c_emod[9]  = {0, 0, 1, 1, 1, 2, 2, 3, 3};
__constant__ int c_ewoff[9] = {0, 2, 3, 4, 5, 6, 8, 9, 11};
__constant__ int c_eslot[9] = {0, 2, 0, 1, 2, 0, 2, 0, 2};
__constant__ int c_ebias[9] = {3, 5, 9, 10, 11, 15, 17, 21, 23};

__global__ __launch_bounds__(256, 3) void qkv_mma(Params p) {
    extern __shared__ __align__(16) char smem_raw[];
    const uint32_t sb = smem_to_u32(smem_raw);

    const int tid = threadIdx.x;
    int bid = blockIdx.x;
    const int mtile = bid % 5; bid /= 5;
    const int e     = bid % 9; bid /= 9;
    const int b     = bid;
    const int mod   = c_emod[e];

    const int Cin = (mod == 1) ? 1280 : 640;
    const int nch = Cin >> 5;
    const int mbase = mtile * 128;

    const int c0m_tab[4] = {2560, 640, 1920, 0};
    const size_t woff = c_offs[c_ewoff[e]];
    const size_t xoff = (size_t)b * 320000 + c0m_tab[mod];
    const float* __restrict__ bias = p.w[c_ebias[e]];
    float* __restrict__ O = g_scr + ((((size_t)b * 4 + mod) * 3 + c_eslot[e]) * 640 + mbase) * 100;

    const __nv_bfloat16* __restrict__ Wh = g_w_hi + woff;
    const __nv_bfloat16* __restrict__ Wl = g_w_lo + woff;
    const __nv_bfloat16* __restrict__ Xh = g_xt_hi + xoff;
    const __nv_bfloat16* __restrict__ Xl = g_xt_lo + xoff;

    // zero B pad rows 100..103 (both stages, hi+lo) — before first barrier
    for (int idx = tid; idx < 320; idx += 256) {
        int st = idx / 160, rest = idx % 160;
        int buf = rest / 80, r2 = rest % 80;
        uint32_t a = sb + (uint32_t)st * STAGE + (buf ? OFF_BL : OFF_BH)
                   + (uint32_t)(100 + r2 / 20) * 80 + (uint32_t)(r2 % 20) * 4;
        asm volatile("st.shared.b32 [%0], %1;" :: "r"(a), "r"(0) : "memory");
    }

    auto issue_chunk = [&](int st, int c) {
        const int k0 = c << 5;
        const uint32_t stg = sb + (uint32_t)st * STAGE;
        for (int idx = tid; idx < 1824; idx += 256) {
            const __nv_bfloat16* src;
            uint32_t dst;
            if (idx < 1024) {
                int buf = idx >> 9, r = (idx >> 2) & 127, seg = idx & 3;
                src = (buf ? Wl : Wh) + (size_t)(mbase + r) * Cin + k0 + seg * 8;
                dst = stg + (buf ? OFF_AL : OFF_AH) + (uint32_t)r * 80 + (uint32_t)seg * 16;
            } else {
                int j = idx - 1024;
                int n = j >> 3, rem = j & 7;
                int buf = rem >> 2, seg = rem & 3;
                src = (buf ? Xl : Xh) + (size_t)n * 3200 + k0 + seg * 8;
                dst = stg + (buf ? OFF_BL : OFF_BH) + (uint32_t)n * 80 + (uint32_t)seg * 16;
            }
            asm volatile("cp.async.cg.shared.global [%0], [%1], 16;" :: "r"(dst), "l"(src) : "memory");
        }
        asm volatile("cp.async.commit_group;" ::: "memory");
    };

    const int w = tid >> 5, lane = tid & 31;
    const int rloc = w * 16 + (lane >> 2);
    const int qd = lane & 3;

    const uint32_t aoff = (uint32_t)(w * 16 + (lane & 15)) * 80 + (uint32_t)(lane >> 4) * 16;
    const uint32_t b4off = (uint32_t)(((lane >> 4) * 8) + (lane & 7)) * 80 + (uint32_t)((lane >> 3) & 1) * 16;
    const uint32_t b2off = (uint32_t)(lane & 7) * 80 + (uint32_t)((lane >> 3) & 1) * 16;

    float acc[13][4];
    #pragma unroll
    for (int t = 0; t < 13; t++)
        #pragma unroll
        for (int i = 0; i < 4; i++) acc[t][i] = 0.0f;

    issue_chunk(0, 0);

    for (int c = 0; c < nch; c++) {
        const int s = c & 1;
        // chunk c is the only pending group; wait for it
        asm volatile("cp.async.wait_group 0;" ::: "memory");
        // all warps: chunk c visible AND iter c-1 MMA (buffer s^1) complete
        __syncthreads();
        if (c + 1 < nch) issue_chunk(s ^ 1, c + 1);

        const uint32_t stg = sb + (uint32_t)s * STAGE;
        const uint32_t aAh = stg + OFF_AH + aoff;
        const uint32_t aAl = stg + OFF_AL + aoff;
        const uint32_t aBh4 = stg + OFF_BH + b4off;
        const uint32_t aBl4 = stg + OFF_BL + b4off;
        const uint32_t aBh2 = stg + OFF_BH + 7680u + b2off;
        const uint32_t aBl2 = stg + OFF_BL + 7680u + b2off;

        #pragma unroll
        for (int s16 = 0; s16 < 2; s16++) {
            const uint32_t ko = (uint32_t)s16 * 32;
            uint32_t ah[4], al[4];
            ldsm4(ah, aAh + ko);
            ldsm4(al, aAl + ko);
            #pragma unroll
            for (int pr = 0; pr < 6; pr++) {
                uint32_t bh[4], bl[4];
                ldsm4(bh, aBh4 + (uint32_t)pr * 1280 + ko);
                ldsm4(bl, aBl4 + (uint32_t)pr * 1280 + ko);
                mma16816(acc[2 * pr],     ah, bh[0], bh[1]);
                mma16816(acc[2 * pr + 1], ah, bh[2], bh[3]);
                mma16816(acc[2 * pr],     ah, bl[0], bl[1]);
                mma16816(acc[2 * pr + 1], ah, bl[2], bl[3]);
                mma16816(acc[2 * pr],     al, bh[0], bh[1]);
                mma16816(acc[2 * pr + 1], al, bh[2], bh[3]);
            }
            {
                uint32_t bh[2], bl[2];
                ldsm2(bh, aBh2 + ko);
                ldsm2(bl, aBl2 + ko);
                mma16816(acc[12], ah, bh[0], bh[1]);
                mma16816(acc[12], ah, bl[0], bl[1]);
                mma16816(acc[12], al, bh[0], bh[1]);
            }
        }
    }

    const float bv0 = bias[mbase + rloc];
    const float bv1 = bias[mbase + rloc + 8];
    float* o0 = O + (size_t)rloc * 100;
    float* o1 = o0 + 800;
    #pragma unroll
    for (int t = 0; t < 13; t++) {
        int col = t * 8 + qd * 2;
        if (col < 100) {
            float2 v0 = make_float2(acc[t][0] + bv0, acc[t][1] + bv0);
            float2 v1 = make_float2(acc[t][2] + bv1, acc[t][3] + bv1);
            *(float2*)(o0 + col) = v0;
            *(float2*)(o1 + col) = v1;
        }
    }
}

// ============================================================================
// Pass 2: attention v4 — EXACT R9 body (best measured).
// ============================================================================
#define PT_OFF   0
#define U_OFF    10000
#define KC_OFF   3328
#define PART_OFF 16656
#define ROW_OFF  17656
#define ATTN_SMEM 71040

__global__ __launch_bounds__(256, 3) void attn_kernel(const float* __restrict__ x,
                                                      float* __restrict__ out) {
    extern __shared__ __align__(16) float sm[];
    const int tid = threadIdx.x;
    const int bm = blockIdx.x;
    const int mod = bm & 3, b = bm >> 2;

    const float* __restrict__ S0 = g_scr + (size_t)bm * 192000;
    const int c0m_tab[4] = {2560, 640, 1920, 0};
    const float* __restrict__ Qp = (mod == 1)
        ? S0
        : (x + (size_t)b * 320000 + (size_t)c0m_tab[mod] * 100);
    const float* __restrict__ Kp = (mod == 1) ? (S0 + 64000) : S0;
    const float* __restrict__ V = S0 + 128000;
    float* __restrict__ O = out + ((size_t)mod * NB + b) * 64000;

    float* Pt   = sm + PT_OFF;
    float* U    = sm + U_OFF;
    float* part = sm + PART_OFF;
    float* row  = sm + ROW_OFF;
    const uint32_t u_b = smem_to_u32(U);
    const uint32_t pt_b = smem_to_u32(Pt);

    const bool act = tid < 250;
    const int lg = tid % 25;
    const int mg = tid / 25;
    const int m0 = mg * 10;

    unsigned long long acc[4][5];
    #pragma unroll
    for (int t = 0; t < 4; t++)
        #pragma unroll
        for (int j = 0; j < 5; j++) acc[t][j] = 0ULL;

    for (int c0 = 0; c0 < 640; c0 += 32) {
        for (int idx = tid; idx < 1600; idx += 256) {
            int which = idx >= 800;
            int i2 = idx - which * 800;
            int rw = i2 / 25, c4 = (i2 % 25) * 4;
            const float* src = (which ? Kp : Qp) + (size_t)(c0 + rw) * 100 + c4;
            *(float4*)(U + which * KC_OFF + rw * 104 + c4) = *(const float4*)src;
        }
        __syncthreads();
        if (act) {
            #pragma unroll 2
            for (int kk = 0; kk < 32; kk++) {
                const float* qrow = U + kk * 104;
                unsigned long long qd_[4];
                #pragma unroll
                for (int t = 0; t < 4; t++) {
                    float qv = qrow[lg + 25 * t];
                    qd_[t] = pack2(qv, qv);
                }
                const uint32_t kb = u_b + (uint32_t)(KC_OFF + kk * 104 + m0) * 4;
                #pragma unroll
                for (int j = 0; j < 5; j++) {
                    unsigned long long kv = lds_u64(kb + (uint32_t)j * 8);
                    ffma2(acc[0][j], qd_[0], kv);
                    ffma2(acc[1][j], qd_[1], kv);
                    ffma2(acc[2][j], qd_[2], kv);
                    ffma2(acc[3][j], qd_[3], kv);
                }
            }
        }
        __syncthreads();
    }

    if (act) {
        #pragma unroll
        for (int t = 0; t < 4; t++) {
            float mx = -3.4e38f;
            #pragma unroll
            for (int j = 0; j < 5; j++) {
                float lo, hi;
                unpack2(acc[t][j], lo, hi);
                mx = fmaxf(mx, fmaxf(lo, hi));
            }
            part[(lg + 25 * t) * 10 + mg] = mx;
        }
    }
    __syncthreads();
    if (tid < 100) {
        float m = -3.4e38f;
        #pragma unroll
        for (int g = 0; g < 10; g++) m = fmaxf(m, part[tid * 10 + g]);
        row[tid] = m;
    }
    __syncthreads();
    if (act) {
        #pragma unroll
        for (int t = 0; t < 4; t++) {
            float mr = row[lg + 25 * t];
            float s = 0.0f;
            #pragma unroll
            for (int j = 0; j < 5; j++) {
                float lo, hi;
                unpack2(acc[t][j], lo, hi);
                float e0 = __expf(lo - mr), e1 = __expf(hi - mr);
                s += e0 + e1;
                acc[t][j] = pack2(e0, e1);
            }
            part[(lg + 25 * t) * 10 + mg] = s;
        }
    }
    __syncthreads();
    if (tid < 100) {
        float s = 0.0f;
        #pragma unroll
        for (int g = 0; g < 10; g++) s += part[tid * 10 + g];
        row[tid] = 1.0f / s;
    }
    __syncthreads();
    if (act) {
        #pragma unroll
        for (int t = 0; t < 4; t++) {
            int l = lg + 25 * t;
            float inv = row[l];
            #pragma unroll
            for (int j = 0; j < 5; j++) {
                float lo, hi;
                unpack2(acc[t][j], lo, hi);
                int m = m0 + 2 * j;
                Pt[m * 100 + l]       = lo * inv;
                Pt[(m + 1) * 100 + l] = hi * inv;
            }
        }
    }

    const int cgC = tid % 16, igC = tid / 16;
    const bool actC = igC < 10;
    const int i0 = igC * 10;

    for (int chunk = 0; chunk < 10; chunk++) {
        __syncthreads();
        for (int idx = tid; idx < 1600; idx += 256) {
            int rw = idx / 25, c4 = (idx % 25) * 4;
            *(float4*)(U + rw * 100 + c4) =
                *(const float4*)(V + (size_t)(chunk * 64 + rw) * 100 + c4);
        }
        __syncthreads();
        if (actC) {
            unsigned long long pacc[4][5];
            #pragma unroll
            for (int u = 0; u < 4; u++)
                #pragma unroll
                for (int s = 0; s < 5; s++) pacc[u][s] = 0ULL;
            const uint32_t pb = pt_b + (uint32_t)i0 * 4;
            #pragma unroll 4
            for (int j = 0; j < 100; j++) {
                unsigned long long vd[4];
                #pragma unroll
                for (int u = 0; u < 4; u++) {
                    float vv = U[(cgC + 16 * u) * 100 + j];
                    vd[u] = pack2(vv, vv);
                }
                const uint32_t pj = pb + (uint32_t)j * 400;
                #pragma unroll
                for (int s = 0; s < 5; s++) {
                    unsigned long long pp = lds_u64(pj + (uint32_t)s * 8);
                    ffma2(pacc[0][s], vd[0], pp);
                    ffma2(pacc[1][s], vd[1], pp);
                    ffma2(pacc[2][s], vd[2], pp);
                    ffma2(pacc[3][s], vd[3], pp);
                }
            }
            #pragma unroll
            for (int u = 0; u < 4; u++) {
                int c_ = chunk * 64 + cgC + 16 * u;
                float* orow = O + (size_t)c_ * 100 + i0;
                #pragma unroll
                for (int s = 0; s < 5; s++) {
                    float a0, a1;
                    unpack2(pacc[u][s], a0, a1);
                    *(float2*)(orow + 2 * s) = make_float2(a0, a1);
                }
            }
        }
    }
}

extern "C" void kernel_launch(void* const* d_in, const int* in_sizes, int n_in,
                              void* d_out, int out_size) {
    const float* x = (const float*)d_in[0];
    float* out = (float*)d_out;
    Params p;
    for (int i = 0; i < 24; i++) p.w[i] = (const float*)d_in[1 + i];

    cudaFuncSetAttribute(qkv_mma, cudaFuncAttributeMaxDynamicSharedMemorySize, 74240);
    cudaFuncSetAttribute(qkv_mma, cudaFuncAttributePreferredSharedMemoryCarveout, 100);
    cudaFuncSetAttribute(attn_kernel, cudaFuncAttributeMaxDynamicSharedMemorySize, ATTN_SMEM);

    // Independent preps run concurrently; join before qkv.
    cudaStream_t s2, s3;
    cudaStreamCreateWithFlags(&s2, cudaStreamNonBlocking);
    cudaStreamCreateWithFlags(&s3, cudaStreamNonBlocking);
    cudaEvent_t evFork, evW, evM;
    cudaEventCreateWithFlags(&evFork, cudaEventDisableTiming);
    cudaEventCreateWithFlags(&evW, cudaEventDisableTiming);
    cudaEventCreateWithFlags(&evM, cudaEventDisableTiming);

    cudaEventRecord(evFork, 0);
    cudaStreamWaitEvent(s2, evFork, 0);
    cudaStreamWaitEvent(s3, evFork, 0);

    prep_w<<<dim3(800, 6), 256, 0, s2>>>(p);
    cudaEventRecord(evW, s2);
    prep_mm<<<dim3(100, 3), 256, 0, s3>>>(p);
    cudaEventRecord(evM, s3);
    prep_x<<<dim3(100, 4, 256), dim3(32, 8)>>>(x);

    cudaStreamWaitEvent(0, evW, 0);
    cudaStreamWaitEvent(0, evM, 0);

    qkv_mma<<<11520, 256, 74240>>>(p);
    attn_kernel<<<1024, 256, ATTN_SMEM>>>(x, out);

    cudaEventDestroy(evFork);
    cudaEventDestroy(evW);
    cudaEventDestroy(evM);
    cudaStreamDestroy(s2);
    cudaStreamDestroy(s3);
}

// round 17
// speedup vs baseline: 1.0931x; 1.0381x over previous
#include <cuda_runtime.h>
#include <cuda_bf16.h>
#include <cstdint>

#define NB 256

// Scratch: [b][mod][slot(0,1,2)][640][100] fp32 (slot2 now unused for V)
__device__ float g_scr[196608000UL];
__device__ __nv_bfloat16 g_w_hi[6144000];
__device__ __nv_bfloat16 g_w_lo[6144000];
__device__ __nv_bfloat16 g_xt_hi[81920000UL];   // [b][l=100][c=3200]
__device__ __nv_bfloat16 g_xt_lo[81920000UL];
// V in bf16 split: [bm=b*4+mod][640][112] (cols 100..111 zero)
__device__ __nv_bfloat16 g_v_hi[73400320UL];
__device__ __nv_bfloat16 g_v_lo[73400320UL];

struct Params {
    const float* w[24];  // [mod][wq,wk,wv,bq,bk,bv]
};

__constant__ size_t c_offs[12] = {0, 409600, 819200, 1228800, 2048000, 2867200,
                                  3686400, 4096000, 4505600, 4915200, 5324800, 5734400};

// ---------------------------------------------------------------- helpers
__device__ __forceinline__ uint32_t smem_to_u32(const void* p) {
    uint32_t a;
    asm("{ .reg .u64 t; cvta.to.shared.u64 t, %1; cvt.u32.u64 %0, t; }" : "=r"(a) : "l"(p));
    return a;
}
__device__ __forceinline__ void ldsm4(uint32_t* r, uint32_t addr) {
    asm volatile("ldmatrix.sync.aligned.m8n8.x4.shared.b16 {%0,%1,%2,%3}, [%4];"
        : "=r"(r[0]), "=r"(r[1]), "=r"(r[2]), "=r"(r[3]) : "r"(addr));
}
__device__ __forceinline__ void ldsm2(uint32_t* r, uint32_t addr) {
    asm volatile("ldmatrix.sync.aligned.m8n8.x2.shared.b16 {%0,%1}, [%2];"
        : "=r"(r[0]), "=r"(r[1]) : "r"(addr));
}
__device__ __forceinline__ void mma16816(float* c, const uint32_t* a, uint32_t b0, uint32_t b1) {
    asm volatile("mma.sync.aligned.m16n8k16.row.col.f32.bf16.bf16.f32 "
        "{%0,%1,%2,%3}, {%4,%5,%6,%7}, {%8,%9}, {%0,%1,%2,%3};"
        : "+f"(c[0]), "+f"(c[1]), "+f"(c[2]), "+f"(c[3])
        : "r"(a[0]), "r"(a[1]), "r"(a[2]), "r"(a[3]), "r"(b0), "r"(b1));
}
__device__ __forceinline__ unsigned long long pack2(float x, float y) {
    unsigned long long r;
    asm("mov.b64 %0, {%1, %2};" : "=l"(r) : "f"(x), "f"(y));
    return r;
}
__device__ __forceinline__ void unpack2(unsigned long long v, float& x, float& y) {
    asm("mov.b64 {%0, %1}, %2;" : "=f"(x), "=f"(y) : "l"(v));
}
__device__ __forceinline__ void ffma2(unsigned long long& c, unsigned long long a, unsigned long long b) {
    asm("fma.rn.f32x2 %0, %1, %2, %0;" : "+l"(c) : "l"(a), "l"(b));
}
__device__ __forceinline__ unsigned long long lds_u64(uint32_t a) {
    unsigned long long v;
    asm volatile("ld.shared.b64 %0, [%1];" : "=l"(v) : "r"(a));
    return v;
}

// ============================================================================
// prep_w: fp32 weights -> bf16 hi/lo (wv all mods + thigh wq,wk)
// ============================================================================
__global__ void prep_w(Params p) {
    const int seg_tab[6] = {2, 3, 4, 5, 8, 11};
    const int seg = seg_tab[blockIdx.y];
    const int mod = seg / 3;
    const int Cin = (mod == 1) ? 1280 : 640;
    const float* __restrict__ w = p.w[mod * 6 + (seg % 3)];
    const size_t off = c_offs[seg];
    const size_t n = (size_t)640 * Cin;
    for (size_t i = (size_t)blockIdx.x * blockDim.x + threadIdx.x; i < n; i += (size_t)gridDim.x * blockDim.x) {
        float v = w[i];
        __nv_bfloat16 h = __float2bfloat16(v);
        g_w_hi[off + i] = h;
        g_w_lo[off + i] = __float2bfloat16(v - __bfloat162float(h));
    }
}

// ============================================================================
// prep_mm: M = Wq^T Wk -> bf16 hi/lo (mods 0,2,3)
// ============================================================================
__global__ __launch_bounds__(256) void prep_mm(Params p) {
    const int mod_tab[3] = {0, 2, 3};
    const int mod = mod_tab[blockIdx.y];
    const float* __restrict__ Wq = p.w[mod * 6 + 0];
    const float* __restrict__ Wk = p.w[mod * 6 + 1];
    const size_t moff = c_offs[mod * 3];

    const int tile = blockIdx.x;
    const int i0 = (tile / 10) * 64, j0 = (tile % 10) * 64;
    const int tid = threadIdx.x;

    __shared__ __align__(16) float Aq[32][68];
    __shared__ __align__(16) float Ak[32][68];

    const int ti = (tid / 16) * 4, tj = (tid % 16) * 4;
    float acc[4][4] = {};

    for (int o0 = 0; o0 < 640; o0 += 32) {
        for (int idx = tid; idx < 512; idx += 256) {
            int r = idx / 16, c4 = (idx % 16) * 4;
            *(float4*)&Aq[r][c4] = *(const float4*)(Wq + (size_t)(o0 + r) * 640 + i0 + c4);
            *(float4*)&Ak[r][c4] = *(const float4*)(Wk + (size_t)(o0 + r) * 640 + j0 + c4);
        }
        __syncthreads();
        #pragma unroll 8
        for (int o = 0; o < 32; o++) {
            float a[4], bv[4];
            #pragma unroll
            for (int ii = 0; ii < 4; ii++) a[ii] = Aq[o][ti + ii];
            #pragma unroll
            for (int jj = 0; jj < 4; jj++) bv[jj] = Ak[o][tj + jj];
            #pragma unroll
            for (int ii = 0; ii < 4; ii++)
                #pragma unroll
                for (int jj = 0; jj < 4; jj++) acc[ii][jj] += a[ii] * bv[jj];
        }
        __syncthreads();
    }

    #pragma unroll
    for (int ii = 0; ii < 4; ii++)
        #pragma unroll
        for (int jj = 0; jj < 4; jj++) {
            float v = acc[ii][jj];
            __nv_bfloat16 h = __float2bfloat16(v);
            size_t o = moff + (size_t)(i0 + ti + ii) * 640 + j0 + tj + jj;
            g_w_hi[o] = h;
            g_w_lo[o] = __float2bfloat16(v - __bfloat162float(h));
        }
}

// ============================================================================
// prep_x: x -> XT bf16 hi/lo
// ============================================================================
__global__ void prep_x(const float* __restrict__ x) {
    __shared__ float t[32][33];
    const int b = blockIdx.z, ct = blockIdx.x, lt = blockIdx.y;
    const int tx = threadIdx.x, ty = threadIdx.y;
    const float* xb = x + (size_t)b * 320000;
    const int l = lt * 32 + tx;
    #pragma unroll
    for (int j = 0; j < 4; j++) {
        int c = ct * 32 + ty + j * 8;
        t[ty + j * 8][tx] = (l < 100) ? xb[(size_t)c * 100 + l] : 0.0f;
    }
    __syncthreads();
    const int c_out = ct * 32 + tx;
    const size_t xtb = (size_t)b * 320000;
    #pragma unroll
    for (int j = 0; j < 4; j++) {
        int lo_ = lt * 32 + ty + j * 8;
        if (lo_ < 100) {
            float v = t[tx][ty + j * 8];
            __nv_bfloat16 h = __float2bfloat16(v);
            size_t o = xtb + (size_t)lo_ * 3200 + c_out;
            g_xt_hi[o] = h;
            g_xt_lo[o] = __float2bfloat16(v - __bfloat162float(h));
        }
    }
}

// ============================================================================
// qkv_mma: R16 body.  slot2 (V) entries emit bf16 hi/lo to g_v instead of
// fp32 scratch (cols 100..111 zero-padded).
// ============================================================================
#define STAGE  37120u
#define OFF_AH 0u
#define OFF_AL 10240u
#define OFF_BH 20480u
#define OFF_BL 28800u

__constant__ int c_emod[9]  = {0, 0, 1, 1, 1, 2, 2, 3, 3};
__constant__ int c_ewoff[9] = {0, 2, 3, 4, 5, 6, 8, 9, 11};
__constant__ int c_eslot[9] = {0, 2, 0, 1, 2, 0, 2, 0, 2};
__constant__ int c_ebias[9] = {3, 5, 9, 10, 11, 15, 17, 21, 23};

__global__ __launch_bounds__(256, 3) void qkv_mma(Params p) {
    extern __shared__ __align__(16) char smem_raw[];
    const uint32_t sb = smem_to_u32(smem_raw);

    const int tid = threadIdx.x;
    int bid = blockIdx.x;
    const int mtile = bid % 5; bid /= 5;
    const int e     = bid % 9; bid /= 9;
    const int b     = bid;
    const int mod   = c_emod[e];

    const int Cin = (mod == 1) ? 1280 : 640;
    const int nch = Cin >> 5;
    const int mbase = mtile * 128;

    const int c0m_tab[4] = {2560, 640, 1920, 0};
    const size_t woff = c_offs[c_ewoff[e]];
    const size_t xoff = (size_t)b * 320000 + c0m_tab[mod];
    const float* __restrict__ bias = p.w[c_ebias[e]];
    float* __restrict__ O = g_scr + ((((size_t)b * 4 + mod) * 3 + c_eslot[e]) * 640 + mbase) * 100;

    const __nv_bfloat16* __restrict__ Wh = g_w_hi + woff;
    const __nv_bfloat16* __restrict__ Wl = g_w_lo + woff;
    const __nv_bfloat16* __restrict__ Xh = g_xt_hi + xoff;
    const __nv_bfloat16* __restrict__ Xl = g_xt_lo + xoff;

    for (int idx = tid; idx < 320; idx += 256) {
        int st = idx / 160, rest = idx % 160;
        int buf = rest / 80, r2 = rest % 80;
        uint32_t a = sb + (uint32_t)st * STAGE + (buf ? OFF_BL : OFF_BH)
                   + (uint32_t)(100 + r2 / 20) * 80 + (uint32_t)(r2 % 20) * 4;
        asm volatile("st.shared.b32 [%0], %1;" :: "r"(a), "r"(0) : "memory");
    }

    auto issue_chunk = [&](int st, int c) {
        const int k0 = c << 5;
        const uint32_t stg = sb + (uint32_t)st * STAGE;
        for (int idx = tid; idx < 1824; idx += 256) {
            const __nv_bfloat16* src;
            uint32_t dst;
            if (idx < 1024) {
                int buf = idx >> 9, r = (idx >> 2) & 127, seg = idx & 3;
                src = (buf ? Wl : Wh) + (size_t)(mbase + r) * Cin + k0 + seg * 8;
                dst = stg + (buf ? OFF_AL : OFF_AH) + (uint32_t)r * 80 + (uint32_t)seg * 16;
            } else {
                int j = idx - 1024;
                int n = j >> 3, rem = j & 7;
                int buf = rem >> 2, seg = rem & 3;
                src = (buf ? Xl : Xh) + (size_t)n * 3200 + k0 + seg * 8;
                dst = stg + (buf ? OFF_BL : OFF_BH) + (uint32_t)n * 80 + (uint32_t)seg * 16;
            }
            asm volatile("cp.async.cg.shared.global [%0], [%1], 16;" :: "r"(dst), "l"(src) : "memory");
        }
        asm volatile("cp.async.commit_group;" ::: "memory");
    };

    const int w = tid >> 5, lane = tid & 31;
    const int rloc = w * 16 + (lane >> 2);
    const int qd = lane & 3;

    const uint32_t aoff = (uint32_t)(w * 16 + (lane & 15)) * 80 + (uint32_t)(lane >> 4) * 16;
    const uint32_t b4off = (uint32_t)(((lane >> 4) * 8) + (lane & 7)) * 80 + (uint32_t)((lane >> 3) & 1) * 16;
    const uint32_t b2off = (uint32_t)(lane & 7) * 80 + (uint32_t)((lane >> 3) & 1) * 16;

    float acc[13][4];
    #pragma unroll
    for (int t = 0; t < 13; t++)
        #pragma unroll
        for (int i = 0; i < 4; i++) acc[t][i] = 0.0f;

    issue_chunk(0, 0);

    for (int c = 0; c < nch; c++) {
        const int s = c & 1;
        asm volatile("cp.async.wait_group 0;" ::: "memory");
        __syncthreads();
        if (c + 1 < nch) issue_chunk(s ^ 1, c + 1);

        const uint32_t stg = sb + (uint32_t)s * STAGE;
        const uint32_t aAh = stg + OFF_AH + aoff;
        const uint32_t aAl = stg + OFF_AL + aoff;
        const uint32_t aBh4 = stg + OFF_BH + b4off;
        const uint32_t aBl4 = stg + OFF_BL + b4off;
        const uint32_t aBh2 = stg + OFF_BH + 7680u + b2off;
        const uint32_t aBl2 = stg + OFF_BL + 7680u + b2off;

        #pragma unroll
        for (int s16 = 0; s16 < 2; s16++) {
            const uint32_t ko = (uint32_t)s16 * 32;
            uint32_t ah[4], al[4];
            ldsm4(ah, aAh + ko);
            ldsm4(al, aAl + ko);
            #pragma unroll
            for (int pr = 0; pr < 6; pr++) {
                uint32_t bh[4], bl[4];
                ldsm4(bh, aBh4 + (uint32_t)pr * 1280 + ko);
                ldsm4(bl, aBl4 + (uint32_t)pr * 1280 + ko);
                mma16816(acc[2 * pr],     ah, bh[0], bh[1]);
                mma16816(acc[2 * pr + 1], ah, bh[2], bh[3]);
                mma16816(acc[2 * pr],     ah, bl[0], bl[1]);
                mma16816(acc[2 * pr + 1], ah, bl[2], bl[3]);
                mma16816(acc[2 * pr],     al, bh[0], bh[1]);
                mma16816(acc[2 * pr + 1], al, bh[2], bh[3]);
            }
            {
                uint32_t bh[2], bl[2];
                ldsm2(bh, aBh2 + ko);
                ldsm2(bl, aBl2 + ko);
                mma16816(acc[12], ah, bh[0], bh[1]);
                mma16816(acc[12], ah, bl[0], bl[1]);
                mma16816(acc[12], al, bh[0], bh[1]);
            }
        }
    }

    const float bv0 = bias[mbase + rloc];
    const float bv1 = bias[mbase + rloc + 8];

    if (c_eslot[e] == 2) {
        // V: write bf16 hi/lo split (for tensor-core phase C)
        __nv_bfloat16* vh = g_v_hi + ((size_t)(b * 4 + mod) * 640 + mbase) * 112;
        __nv_bfloat16* vl = g_v_lo + ((size_t)(b * 4 + mod) * 640 + mbase) * 112;
        #pragma unroll
        for (int t = 0; t < 13; t++) {
            int col = t * 8 + qd * 2;
            if (col < 100) {
                float v00 = acc[t][0] + bv0, v01 = acc[t][1] + bv0;
                float v10 = acc[t][2] + bv1, v11 = acc[t][3] + bv1;
                __nv_bfloat162 h0, l0, h1, l1;
                h0.x = __float2bfloat16(v00); l0.x = __float2bfloat16(v00 - __bfloat162float(h0.x));
                h0.y = __float2bfloat16(v01); l0.y = __float2bfloat16(v01 - __bfloat162float(h0.y));
                h1.x = __float2bfloat16(v10); l1.x = __float2bfloat16(v10 - __bfloat162float(h1.x));
                h1.y = __float2bfloat16(v11); l1.y = __float2bfloat16(v11 - __bfloat162float(h1.y));
                *(__nv_bfloat162*)(vh + (size_t)rloc * 112 + col) = h0;
                *(__nv_bfloat162*)(vl + (size_t)rloc * 112 + col) = l0;
                *(__nv_bfloat162*)(vh + (size_t)(rloc + 8) * 112 + col) = h1;
                *(__nv_bfloat162*)(vl + (size_t)(rloc + 8) * 112 + col) = l1;
            }
        }
        // zero pad cols 100..111 (6 x bf162 per row, 128 rows)
        for (int idx = tid; idx < 768; idx += 256) {
            int r = idx / 6, c2 = 100 + (idx % 6) * 2;
            *(uint32_t*)(vh + (size_t)r * 112 + c2) = 0u;
            *(uint32_t*)(vl + (size_t)r * 112 + c2) = 0u;
        }
    } else {
        float* o0 = O + (size_t)rloc * 100;
        float* o1 = o0 + 800;
        #pragma unroll
        for (int t = 0; t < 13; t++) {
            int col = t * 8 + qd * 2;
            if (col < 100) {
                *(float2*)(o0 + col) = make_float2(acc[t][0] + bv0, acc[t][1] + bv0);
                *(float2*)(o1 + col) = make_float2(acc[t][2] + bv1, acc[t][3] + bv1);
            }
        }
    }
}

// ============================================================================
// Pass 2: attention v5.  Phase A + softmax = R9 body; phase C = tensor-core
// (bf16 3-term split, chunks of 64 V-rows, double-buffered cp.async).
// Smem bytes: Ph[104][120] @0 (24960) | Pl @24960 | alias @49920:
//   phase A: U 26624B + part 4000B + row 400B   (inside 61440B V ring)
//   phase C: V stages 2 x (hi 15360 + lo 15360)
// Total 111360 B -> 2 CTAs/SM.
// ============================================================================
#define ATTN_SMEM 111360

__global__ __launch_bounds__(256, 2) void attn_kernel(const float* __restrict__ x,
                                                      float* __restrict__ out) {
    extern __shared__ __align__(16) float sm[];
    const int tid = threadIdx.x;
    const int bm = blockIdx.x;
    const int mod = bm & 3, b = bm >> 2;

    const float* __restrict__ S0 = g_scr + (size_t)bm * 192000;
    const int c0m_tab[4] = {2560, 640, 1920, 0};
    const float* __restrict__ Qp = (mod == 1)
        ? S0
        : (x + (size_t)b * 320000 + (size_t)c0m_tab[mod] * 100);
    const float* __restrict__ Kp = (mod == 1) ? (S0 + 64000) : S0;
    float* __restrict__ O = out + ((size_t)mod * NB + b) * 64000;

    const uint32_t smb = smem_to_u32(sm);
    const uint32_t phb = smb;            // Ph [104][120] bf16
    const uint32_t plb = smb + 24960;    // Pl
    float* U    = sm + 12480;            // byte 49920
    float* part = sm + 19136;
    float* row  = sm + 20136;
    const uint32_t u_b = smem_to_u32(U);

    // zero P region (rows/cols padding must be 0 for MMA)
    for (int idx = tid; idx < 12480; idx += 256)
        ((uint32_t*)sm)[idx] = 0u;

    // ---- Phase A: S[100,100] = Q^T K, k-chunks of 32 (R9 body) ----
    const bool act = tid < 250;
    const int lg = tid % 25;
    const int mg = tid / 25;
    const int m0 = mg * 10;

    unsigned long long acc[4][5];
    #pragma unroll
    for (int t = 0; t < 4; t++)
        #pragma unroll
        for (int j = 0; j < 5; j++) acc[t][j] = 0ULL;

    for (int c0 = 0; c0 < 640; c0 += 32) {
        for (int idx = tid; idx < 1600; idx += 256) {
            int which = idx >= 800;
            int i2 = idx - which * 800;
            int rw = i2 / 25, c4 = (i2 % 25) * 4;
            const float* src = (which ? Kp : Qp) + (size_t)(c0 + rw) * 100 + c4;
            *(float4*)(U + which * 3328 + rw * 104 + c4) = *(const float4*)src;
        }
        __syncthreads();
        if (act) {
            #pragma unroll 2
            for (int kk = 0; kk < 32; kk++) {
                const float* qrow = U + kk * 104;
                unsigned long long qd_[4];
                #pragma unroll
                for (int t = 0; t < 4; t++) {
                    float qv = qrow[lg + 25 * t];
                    qd_[t] = pack2(qv, qv);
                }
                const uint32_t kb = u_b + (uint32_t)(3328 + kk * 104 + m0) * 4;
                #pragma unroll
                for (int j = 0; j < 5; j++) {
                    unsigned long long kv = lds_u64(kb + (uint32_t)j * 8);
                    ffma2(acc[0][j], qd_[0], kv);
                    ffma2(acc[1][j], qd_[1], kv);
                    ffma2(acc[2][j], qd_[2], kv);
                    ffma2(acc[3][j], qd_[3], kv);
                }
            }
        }
        __syncthreads();
    }

    // ---- Softmax (register-resident S); writes P bf16 hi/lo [l][120] ----
    if (act) {
        #pragma unroll
        for (int t = 0; t < 4; t++) {
            float mx = -3.4e38f;
            #pragma unroll
            for (int j = 0; j < 5; j++) {
                float lo, hi;
                unpack2(acc[t][j], lo, hi);
                mx = fmaxf(mx, fmaxf(lo, hi));
            }
            part[(lg + 25 * t) * 10 + mg] = mx;
        }
    }
    __syncthreads();
    if (tid < 100) {
        float m = -3.4e38f;
        #pragma unroll
        for (int g = 0; g < 10; g++) m = fmaxf(m, part[tid * 10 + g]);
        row[tid] = m;
    }
    __syncthreads();
    if (act) {
        #pragma unroll
        for (int t = 0; t < 4; t++) {
            float mr = row[lg + 25 * t];
            float s = 0.0f;
            #pragma unroll
            for (int j = 0; j < 5; j++) {
                float lo, hi;
                unpack2(acc[t][j], lo, hi);
                float e0 = __expf(lo - mr), e1 = __expf(hi - mr);
                s += e0 + e1;
                acc[t][j] = pack2(e0, e1);
            }
            part[(lg + 25 * t) * 10 + mg] = s;
        }
    }
    __syncthreads();
    if (tid < 100) {
        float s = 0.0f;
        #pragma unroll
        for (int g = 0; g < 10; g++) s += part[tid * 10 + g];
        row[tid] = 1.0f / s;
    }
    __syncthreads();
    if (act) {
        #pragma unroll
        for (int t = 0; t < 4; t++) {
            int l = lg + 25 * t;
            float inv = row[l];
            #pragma unroll
            for (int j = 0; j < 5; j++) {
                float lo, hi;
                unpack2(acc[t][j], lo, hi);
                float p0 = lo * inv, p1 = hi * inv;
                int m = m0 + 2 * j;
                __nv_bfloat162 hh, ll;
                hh.x = __float2bfloat16(p0);
                hh.y = __float2bfloat16(p1);
                ll.x = __float2bfloat16(p0 - __bfloat162float(hh.x));
                ll.y = __float2bfloat16(p1 - __bfloat162float(hh.y));
                *(__nv_bfloat162*)((char*)sm + (size_t)l * 240 + (size_t)m * 2) = hh;
                *(__nv_bfloat162*)((char*)sm + 24960 + (size_t)l * 240 + (size_t)m * 2) = ll;
            }
        }
    }
    __syncthreads();   // P visible; part/row/U dead -> V ring may be filled

    // ---- Phase C: O[640,100] = V @ P^T via mma.sync, 10 chunks of 64 rows ----
    const int wid = tid >> 5, lane = tid & 31;
    const int wm = wid & 3, wn = wid >> 2;       // 4m x 2n warp grid
    const int qd = lane & 3;
    const int ntiles = 7 - wn;                   // wn0: 7 tiles, wn1: 6

    const uint32_t vAoff = (uint32_t)(wm * 16 + (lane & 15)) * 240 + (uint32_t)(lane >> 4) * 16;
    const uint32_t pB4off = (uint32_t)((lane >> 4) * 8 + (lane & 7)) * 240 + (uint32_t)((lane >> 3) & 1) * 16;
    const uint32_t pB2off = (uint32_t)(lane & 7) * 240 + (uint32_t)((lane >> 3) & 1) * 16;
    const uint32_t pNbase = (uint32_t)(wn * 56) * 240;

    auto issue_v = [&](int st, int chunk) {
        const uint32_t vb = smb + 49920u + (uint32_t)st * 30720u;
        const __nv_bfloat16* srcH = g_v_hi + ((size_t)bm * 640 + chunk * 64) * 112;
        const __nv_bfloat16* srcL = g_v_lo + ((size_t)bm * 640 + chunk * 64) * 112;
        for (int idx = tid; idx < 1792; idx += 256) {
            int half = idx >= 896;
            int i2 = idx - half * 896;
            int r = i2 / 14, seg = i2 % 14;
            const __nv_bfloat16* src = (half ? srcL : srcH) + (size_t)r * 112 + seg * 8;
            uint32_t dst = vb + (uint32_t)half * 15360u + (uint32_t)r * 240 + (uint32_t)seg * 16;
            asm volatile("cp.async.cg.shared.global [%0], [%1], 16;" :: "r"(dst), "l"(src) : "memory");
        }
        asm volatile("cp.async.commit_group;" ::: "memory");
    };

    issue_v(0, 0);

    for (int chunk = 0; chunk < 10; chunk++) {
        const int s = chunk & 1;
        asm volatile("cp.async.wait_group 0;" ::: "memory");
        __syncthreads();
        if (chunk + 1 < 10) issue_v(s ^ 1, chunk + 1);

        const uint32_t vb = smb + 49920u + (uint32_t)s * 30720u;
        const uint32_t aVh = vb + vAoff;
        const uint32_t aVl = vb + 15360u + vAoff;

        float cacc[7][4];
        #pragma unroll
        for (int t = 0; t < 7; t++)
            #pragma unroll
            for (int i = 0; i < 4; i++) cacc[t][i] = 0.0f;

        #pragma unroll
        for (int ks = 0; ks < 7; ks++) {
            const uint32_t ko = (uint32_t)ks * 32;
            uint32_t ah[4], al[4];
            ldsm4(ah, aVh + ko);
            ldsm4(al, aVl + ko);
            #pragma unroll
            for (int pr = 0; pr < 3; pr++) {
                uint32_t bh[4], bl[4];
                const uint32_t pb = pNbase + (uint32_t)pr * 3840 + ko;
                ldsm4(bh, phb + pb + pB4off);
                ldsm4(bl, plb + pb + pB4off);
                mma16816(cacc[2 * pr],     ah, bh[0], bh[1]);
                mma16816(cacc[2 * pr + 1], ah, bh[2], bh[3]);
                mma16816(cacc[2 * pr],     ah, bl[0], bl[1]);
                mma16816(cacc[2 * pr + 1], ah, bl[2], bl[3]);
                mma16816(cacc[2 * pr],     al, bh[0], bh[1]);
                mma16816(cacc[2 * pr + 1], al, bh[2], bh[3]);
            }
            if (wn == 0) {
                uint32_t bh[2], bl[2];
                const uint32_t pb = pNbase + 11520u + ko;
                ldsm2(bh, phb + pb + pB2off);
                ldsm2(bl, plb + pb + pB2off);
                mma16816(cacc[6], ah, bh[0], bh[1]);
                mma16816(cacc[6], ah, bl[0], bl[1]);
                mma16816(cacc[6], al, bh[0], bh[1]);
            }
        }

        const int r0 = chunk * 64 + wm * 16 + (lane >> 2);
        float* o0 = O + (size_t)r0 * 100;
        float* o1 = o0 + 800;
        #pragma unroll
        for (int t = 0; t < 7; t++) {
            if (t < ntiles) {
                int col = wn * 56 + t * 8 + qd * 2;
                if (col < 100) {
                    *(float2*)(o0 + col) = make_float2(cacc[t][0], cacc[t][1]);
                    *(float2*)(o1 + col) = make_float2(cacc[t][2], cacc[t][3]);
                }
            }
        }
    }
}

extern "C" void kernel_launch(void* const* d_in, const int* in_sizes, int n_in,
                              void* d_out, int out_size) {
    const float* x = (const float*)d_in[0];
    float* out = (float*)d_out;
    Params p;
    for (int i = 0; i < 24; i++) p.w[i] = (const float*)d_in[1 + i];

    cudaFuncSetAttribute(qkv_mma, cudaFuncAttributeMaxDynamicSharedMemorySize, 74240);
    cudaFuncSetAttribute(qkv_mma, cudaFuncAttributePreferredSharedMemoryCarveout, 100);
    cudaFuncSetAttribute(attn_kernel, cudaFuncAttributeMaxDynamicSharedMemorySize, ATTN_SMEM);
    cudaFuncSetAttribute(attn_kernel, cudaFuncAttributePreferredSharedMemoryCarveout, 100);

    prep_w<<<dim3(800, 6), 256>>>(p);
    prep_mm<<<dim3(100, 3), 256>>>(p);
    prep_x<<<dim3(100, 4, 256), dim3(32, 8)>>>(x);

    qkv_mma<<<11520, 256, 74240>>>(p);
    attn_kernel<<<1024, 256, ATTN_SMEM>>>(x, out);
}